// round 13
// baseline (speedup 1.0000x reference)
#include <cuda_runtime.h>
#include <cuda_fp16.h>
#include <math.h>
#include <stdint.h>

#define EMBED 1024
#define HEADS 16
#define HDIM  64
#define BATCH 2
#define SEQ   2048
#define M_TOT (BATCH*SEQ)   // 4096

// ---------------- scratch (device globals; allocation-free) ----------------
__device__ __align__(16) __half g_xa[M_TOT*EMBED];   // query act / AO
__device__ __align__(16) __half g_xb[M_TOT*EMBED];   // key act
__device__ __align__(16) __half g_xc[M_TOT*EMBED];   // value act
__device__ __align__(16) __half g_w0[EMBED*EMBED];   // Wq
__device__ __align__(16) __half g_w1[EMBED*EMBED];   // Wk
__device__ __align__(16) __half g_w2[EMBED*EMBED];   // Wv
__device__ __align__(16) __half g_w3[EMBED*EMBED];   // Wo
__device__ __align__(16) __half g_q16[BATCH*HEADS*SEQ*HDIM];
__device__ __align__(16) __half g_k16[BATCH*HEADS*SEQ*HDIM];
__device__ __align__(16) __half g_v16[BATCH*HEADS*SEQ*HDIM];

// ---------------------------------------------------------------------------
// fp32 -> fp16, ALL seven tensors in one launch.
// ---------------------------------------------------------------------------
__global__ __launch_bounds__(256) void cvt_all(
    const float* __restrict__ q,  const float* __restrict__ k,
    const float* __restrict__ v,
    const float* __restrict__ wq, const float* __restrict__ wk,
    const float* __restrict__ wv, const float* __restrict__ wo,
    __half* __restrict__ xa, __half* __restrict__ xb, __half* __restrict__ xc,
    __half* __restrict__ w0, __half* __restrict__ w1,
    __half* __restrict__ w2, __half* __restrict__ w3)
{
    const int blk = blockIdx.x;
    const float* x; __half* h; int off;
    if (blk < 1024)      { x = q;  h = xa; off = blk; }
    else if (blk < 2048) { x = k;  h = xb; off = blk - 1024; }
    else if (blk < 3072) { x = v;  h = xc; off = blk - 2048; }
    else if (blk < 3328) { x = wq; h = w0; off = blk - 3072; }
    else if (blk < 3584) { x = wk; h = w1; off = blk - 3328; }
    else if (blk < 3840) { x = wv; h = w2; off = blk - 3584; }
    else                 { x = wo; h = w3; off = blk - 3840; }

    const float4* src = (const float4*)x + (size_t)off * 1024;
    uint2* dst = (uint2*)h + (size_t)off * 1024;
    const int tid = threadIdx.x;
    #pragma unroll
    for (int j = 0; j < 4; j++) {
        float4 vv = src[j * 256 + tid];
        __half2 p = __floats2half2_rn(vv.x, vv.y);
        __half2 qq = __floats2half2_rn(vv.z, vv.w);
        uint2 r;
        r.x = reinterpret_cast<uint32_t&>(p);
        r.y = reinterpret_cast<uint32_t&>(qq);
        dst[j * 256 + tid] = r;
    }
}

// ---------------------------------------------------------------------------
// warp-MMA helpers
// ---------------------------------------------------------------------------
__device__ __forceinline__ uint32_t s2u(const void* p) {
    uint32_t a;
    asm("{ .reg .u64 t; cvta.to.shared.u64 t, %1; cvt.u32.u64 %0, t; }" : "=r"(a) : "l"(p));
    return a;
}

__device__ __forceinline__ void ldmx4(uint32_t& r0, uint32_t& r1, uint32_t& r2, uint32_t& r3,
                                      uint32_t addr)
{
    asm volatile("ldmatrix.sync.aligned.m8n8.x4.shared.b16 {%0,%1,%2,%3}, [%4];"
                 : "=r"(r0), "=r"(r1), "=r"(r2), "=r"(r3) : "r"(addr));
}

__device__ __forceinline__ void ldmx4t(uint32_t& r0, uint32_t& r1, uint32_t& r2, uint32_t& r3,
                                       uint32_t addr)
{
    asm volatile("ldmatrix.sync.aligned.m8n8.x4.trans.shared.b16 {%0,%1,%2,%3}, [%4];"
                 : "=r"(r0), "=r"(r1), "=r"(r2), "=r"(r3) : "r"(addr));
}

__device__ __forceinline__ void mma16816(float* d, const uint32_t* a, const uint32_t* b)
{
    asm volatile("mma.sync.aligned.m16n8k16.row.col.f32.f16.f16.f32 "
                 "{%0,%1,%2,%3}, {%4,%5,%6,%7}, {%8,%9}, {%0,%1,%2,%3};"
                 : "+f"(d[0]), "+f"(d[1]), "+f"(d[2]), "+f"(d[3])
                 : "r"(a[0]), "r"(a[1]), "r"(a[2]), "r"(a[3]), "r"(b[0]), "r"(b[1]));
}

__device__ __forceinline__ void cpasync16(uint32_t saddr, const void* gaddr)
{
    asm volatile("cp.async.cg.shared.global [%0], [%1], 16;" :: "r"(saddr), "l"(gaddr));
}

__device__ __forceinline__ uint32_t swz(uint32_t off) { return off ^ ((off >> 3) & 0x70); }

__device__ __forceinline__ uint32_t pack_h2(float x, float y) {
    __half2 t = __floats2half2_rn(x, y);
    return reinterpret_cast<uint32_t&>(t);
}

__device__ __forceinline__ uint32_t exp2_h2(float t0, float t1) {
    uint32_t r;
    asm("{ .reg .b32 t; cvt.rn.f16x2.f32 t, %2, %1; ex2.approx.f16x2 %0, t; }"
        : "=r"(r) : "f"(t0), "f"(t1));
    return r;
}

// ---------------------------------------------------------------------------
// Tensor-core GEMM (round-9 proven): CTA tile 128x128, BK=64, 8 warps,
// 2-stage pipeline, 2 CTAs/SM. blockIdx.z selects (X, W, out).
// ---------------------------------------------------------------------------
#define GSTG  32768u
#define GSMEM (2 * GSTG)   // 64 KB -> 2 CTAs/SM

template<bool SPLIT>
__global__ __launch_bounds__(256, 2) void gemm_tc(
    const __half* __restrict__ xa, const __half* __restrict__ xb, const __half* __restrict__ xc,
    const __half* __restrict__ wa, const __half* __restrict__ wb, const __half* __restrict__ wc,
    float* __restrict__ out,
    __half* __restrict__ oa, __half* __restrict__ ob, __half* __restrict__ oc)
{
    const int z = blockIdx.z;
    const __half* x16 = (z == 0) ? xa : (z == 1) ? xb : xc;
    const __half* w16 = (z == 0) ? wa : (z == 1) ? wb : wc;
    __half* outh      = (z == 0) ? oa : (z == 1) ? ob : oc;

    extern __shared__ char smg[];
    const uint32_t sb = s2u(smg);
    const int tid  = threadIdx.x;
    const int wid  = tid >> 5, lane = tid & 31;
    const int wm   = wid & 1;
    const int wn   = wid >> 1;
    const int m0   = blockIdx.x * 128;
    const int n0   = blockIdx.y * 128;

    const int ldr = tid >> 3;
    const int ldc = tid & 7;

    auto issue = [&](int c, bool real) {
        if (real) {
            const uint32_t sst = sb + (uint32_t)(c & 1) * GSTG;
            const int kc0 = c * 64;
            const __half* gA = x16 + (size_t)m0 * EMBED + kc0;
            const __half* gB = w16 + (size_t)n0 * EMBED + kc0;
            #pragma unroll
            for (int it = 0; it < 4; it++) {
                const int r = ldr + it * 32;
                const uint32_t o = swz((uint32_t)(r * 128 + ldc * 16));
                const size_t g = (size_t)r * EMBED + ldc * 8;
                cpasync16(sst +          o, gA + g);
                cpasync16(sst + 16384u + o, gB + g);
            }
        }
        asm volatile("cp.async.commit_group;" ::: "memory");
    };

    float d[4][4][4];
    #pragma unroll
    for (int mi = 0; mi < 4; mi++)
        #pragma unroll
        for (int ni = 0; ni < 4; ni++)
            #pragma unroll
            for (int r = 0; r < 4; r++) d[mi][ni][r] = 0.f;

    issue(0, true); issue(1, true);

    const int arow = lane & 15;
    const int akc  = (lane & 16) >> 1;
    const int brow = (lane & 7) | ((lane & 16) >> 1);
    const int bkc  = lane & 8;

    const int NCHUNK = EMBED / 64;   // 16
    for (int c = 0; c < NCHUNK; c++) {
        asm volatile("cp.async.wait_group 1;" ::: "memory");
        __syncthreads();

        const uint32_t sst = sb + (uint32_t)(c & 1) * GSTG;
        const uint32_t bBase = sst + 16384u;

        #pragma unroll
        for (int ks = 0; ks < 4; ks++) {
            uint32_t a[4][4];
            #pragma unroll
            for (int mi = 0; mi < 4; mi++) {
                const int row = wm * 64 + mi * 16 + arow;
                const uint32_t off = swz((uint32_t)(row * 128 + (ks * 16 + akc) * 2));
                ldmx4(a[mi][0], a[mi][1], a[mi][2], a[mi][3], sst + off);
            }
            uint32_t b[4][2];
            #pragma unroll
            for (int bi = 0; bi < 2; bi++) {
                const int row = wn * 32 + bi * 16 + brow;
                const uint32_t off = swz((uint32_t)(row * 128 + (ks * 16 + bkc) * 2));
                uint32_t r0, r1, r2, r3;
                ldmx4(r0, r1, r2, r3, bBase + off);
                b[bi*2  ][0] = r0; b[bi*2  ][1] = r1;
                b[bi*2+1][0] = r2; b[bi*2+1][1] = r3;
            }
            #pragma unroll
            for (int mi = 0; mi < 4; mi++)
                #pragma unroll
                for (int ni = 0; ni < 4; ni++)
                    mma16816(d[mi][ni], a[mi], b[ni]);
        }
        __syncthreads();
        issue(c + 2, c + 2 < NCHUNK);
    }

    const int g4 = lane >> 2, t4 = lane & 3;
    #pragma unroll
    for (int mi = 0; mi < 4; mi++) {
        #pragma unroll
        for (int half = 0; half < 2; half++) {
            const int m = m0 + wm * 64 + mi * 16 + g4 + half * 8;
            const int bb = m >> 11, ssq = m & (SEQ - 1);
            #pragma unroll
            for (int ni = 0; ni < 4; ni++) {
                const int n = n0 + wn * 32 + ni * 8 + t4 * 2;
                const float vx = d[mi][ni][half * 2 + 0];
                const float vy = d[mi][ni][half * 2 + 1];
                if (SPLIT) {
                    const int h = n >> 6, dd = n & 63;
                    const size_t idx = (((size_t)(bb * HEADS + h)) * SEQ + ssq) * HDIM + dd;
                    *(uint32_t*)(outh + idx) = pack_h2(vx, vy);
                } else {
                    float2 v; v.x = vx; v.y = vy;
                    *(float2*)(out + (size_t)m * EMBED + n) = v;
                }
            }
        }
    }
}

// ---------------------------------------------------------------------------
// Flash attention on HMMA. CTA = 256 q-rows x 128-kv tiles: each warp owns
// 32 q-rows (2 mi blocks) -> K/V ldmatrix fragments reused across mi ->
// KV LDS bytes per unit work HALVED vs 128-q CTA. kv processed in 64-halves
// to bound live registers (s[2][8][4]). 1 CTA/SM, 4-stage KV pipeline.
// smem: Q 32KB + 4 x 32KB = 160KB.
// ---------------------------------------------------------------------------
#define FSTG  32768u
#define FSMEM (32768 + 4 * FSTG)       // 160 KB
#define SCLOG2E 0.04508422002474647f   // (1/32) * log2(e)
#define MASK_RAW -3200000.0f           // -100000 / (1/32)

__global__ __launch_bounds__(256, 1) void flash_tc(
    const __half* __restrict__ q16, const __half* __restrict__ k16,
    const __half* __restrict__ v16, __half* __restrict__ oh)
{
    extern __shared__ char smf[];
    const uint32_t sb = s2u(smf);
    const int tid  = threadIdx.x;
    const int wid  = tid >> 5, lane = tid & 31;
    const int g4   = lane >> 2, t4 = lane & 3;
    const int bh   = blockIdx.y;
    const int b    = bh >> 4, head = bh & 15;
    const int qi   = (int)gridDim.x - 1 - (int)blockIdx.x;   // heavy tiles first
    const int q0   = qi * 256;
    const int nkt  = 2 * qi + 2;        // number of 128-kv tiles

    const size_t bo = (size_t)bh * SEQ * HDIM;
    const __half* Qp = q16 + bo + (size_t)q0 * HDIM;
    const __half* Kp = k16 + bo;
    const __half* Vp = v16 + bo;

    const int ldr = tid >> 3, ldc = tid & 7;
    // Q: 256 rows
    auto loadQ = [&]() {
        #pragma unroll
        for (int it = 0; it < 8; it++) {
            const int r = ldr + it * 32;
            cpasync16(sb + swz((uint32_t)(r * 128 + ldc * 16)),
                      Qp + (size_t)r * HDIM + ldc * 8);
        }
    };
    // K/V: 128 rows each per stage
    auto issueKV = [&](int kt, bool real) {
        if (real) {
            const uint32_t st = 32768u + (uint32_t)(kt & 3) * FSTG;
            const size_t off = (size_t)kt * 128 * HDIM;
            #pragma unroll
            for (int it = 0; it < 4; it++) {
                const int r = ldr + it * 32;
                const uint32_t o = swz((uint32_t)(r * 128 + ldc * 16));
                const size_t g = (size_t)r * HDIM + ldc * 8;
                cpasync16(sb + st +          o, Kp + off + g);
                cpasync16(sb + st + 16384u + o, Vp + off + g);
            }
        }
        asm volatile("cp.async.commit_group;" ::: "memory");
    };

    loadQ();                       // bundled into group 0
    issueKV(0, true);
    issueKV(1, 1 < nkt);
    issueKV(2, 2 < nkt);
    issueKV(3, 3 < nkt);

    const int arow = lane & 15;
    const int akc  = (lane & 16) >> 1;
    const int brow = (lane & 7) | ((lane & 16) >> 1);
    const int bkc  = lane & 8;
    const int vrow = lane & 15;
    const int vsel = ((lane >> 4) & 1) * 16;

    // wait for Q (+KV0), hoist Q fragments (32 q rows -> 2 mi blocks)
    asm volatile("cp.async.wait_group 3;" ::: "memory");
    __syncthreads();
    uint32_t qf[2][4][4];
    #pragma unroll
    for (int mi = 0; mi < 2; mi++)
        #pragma unroll
        for (int ks = 0; ks < 4; ks++) {
            const uint32_t offA =
                swz((uint32_t)((wid * 32 + mi * 16 + arow) * 128 + (ks * 16 + akc) * 2));
            ldmx4(qf[mi][ks][0], qf[mi][ks][1], qf[mi][ks][2], qf[mi][ks][3], sb + offA);
        }

    float o[2][8][4];
    #pragma unroll
    for (int mi = 0; mi < 2; mi++)
        #pragma unroll
        for (int ng = 0; ng < 8; ng++)
            #pragma unroll
            for (int r = 0; r < 4; r++) o[mi][ng][r] = 0.f;
    float m_[2][2]  = {{-INFINITY, -INFINITY}, {-INFINITY, -INFINITY}};
    float l32[2][2] = {{0.f, 0.f}, {0.f, 0.f}};

    for (int kt = 0; kt < nkt; kt++) {
        asm volatile("cp.async.wait_group 3;" ::: "memory");
        __syncthreads();

        const uint32_t st = sb + 32768u + (uint32_t)(kt & 3) * FSTG;
        const bool diag = (kt >= nkt - 2);

        #pragma unroll
        for (int hb = 0; hb < 2; hb++) {           // 64-kv half
            const int k0 = kt * 128 + hb * 64;

            // ---- S = Q K^T for both mi (K fragments loaded ONCE) ----
            float s[2][8][4];
            #pragma unroll
            for (int mi = 0; mi < 2; mi++)
                #pragma unroll
                for (int ni = 0; ni < 8; ni++)
                    #pragma unroll
                    for (int r = 0; r < 4; r++) s[mi][ni][r] = 0.f;

            #pragma unroll
            for (int ks = 0; ks < 4; ks++) {
                #pragma unroll
                for (int bi = 0; bi < 4; bi++) {
                    const uint32_t offB =
                        swz((uint32_t)((hb * 64 + bi * 16 + brow) * 128 + (ks * 16 + bkc) * 2));
                    uint32_t r0, r1, r2, r3;
                    ldmx4(r0, r1, r2, r3, st + offB);
                    uint32_t b0[2] = {r0, r1}, b1[2] = {r2, r3};
                    mma16816(s[0][bi*2],   qf[0][ks], b0);
                    mma16816(s[0][bi*2+1], qf[0][ks], b1);
                    mma16816(s[1][bi*2],   qf[1][ks], b0);
                    mma16816(s[1][bi*2+1], qf[1][ks], b1);
                }
            }

            // ---- mask + softmax bookkeeping per mi ----
            if (diag) {
                #pragma unroll
                for (int mi = 0; mi < 2; mi++)
                    #pragma unroll
                    for (int ni = 0; ni < 8; ni++) {
                        const int kg = k0 + ni * 8 + t4 * 2;
                        #pragma unroll
                        for (int h = 0; h < 2; h++) {
                            const int qg = q0 + wid * 32 + mi * 16 + g4 + h * 8;
                            if (kg     > qg) s[mi][ni][h*2+0] += MASK_RAW;
                            if (kg + 1 > qg) s[mi][ni][h*2+1] += MASK_RAW;
                        }
                    }
            }
            #pragma unroll
            for (int mi = 0; mi < 2; mi++)
                #pragma unroll
                for (int h = 0; h < 2; h++) {
                    float mx = -INFINITY;
                    #pragma unroll
                    for (int ni = 0; ni < 8; ni++)
                        mx = fmaxf(mx, fmaxf(s[mi][ni][h*2+0], s[mi][ni][h*2+1]));
                    mx = fmaxf(mx, __shfl_xor_sync(0xffffffffu, mx, 1));
                    mx = fmaxf(mx, __shfl_xor_sync(0xffffffffu, mx, 2));
                    const float mnew = fmaxf(m_[mi][h], mx);
                    const float corr = exp2f((m_[mi][h] - mnew) * SCLOG2E);
                    m_[mi][h] = mnew;
                    l32[mi][h] *= corr;
                    #pragma unroll
                    for (int ng = 0; ng < 8; ng++) {
                        o[mi][ng][h*2+0] *= corr;
                        o[mi][ng][h*2+1] *= corr;
                    }
                }

            // ---- O += P V for both mi (V fragments loaded ONCE) ----
            #pragma unroll
            for (int kc = 0; kc < 4; kc++) {
                uint32_t pa[2][4];
                #pragma unroll
                for (int mi = 0; mi < 2; mi++) {
                    const float lm0 = m_[mi][0] * SCLOG2E;
                    const float lm1 = m_[mi][1] * SCLOG2E;
                    pa[mi][0] = exp2_h2(fmaf(s[mi][kc*2  ][0], SCLOG2E, -lm0),
                                        fmaf(s[mi][kc*2  ][1], SCLOG2E, -lm0));
                    pa[mi][1] = exp2_h2(fmaf(s[mi][kc*2  ][2], SCLOG2E, -lm1),
                                        fmaf(s[mi][kc*2  ][3], SCLOG2E, -lm1));
                    pa[mi][2] = exp2_h2(fmaf(s[mi][kc*2+1][0], SCLOG2E, -lm0),
                                        fmaf(s[mi][kc*2+1][1], SCLOG2E, -lm0));
                    pa[mi][3] = exp2_h2(fmaf(s[mi][kc*2+1][2], SCLOG2E, -lm1),
                                        fmaf(s[mi][kc*2+1][3], SCLOG2E, -lm1));
                    const __half2 p02 = __hadd2(*(const __half2*)&pa[mi][0],
                                                *(const __half2*)&pa[mi][2]);
                    const __half2 p13 = __hadd2(*(const __half2*)&pa[mi][1],
                                                *(const __half2*)&pa[mi][3]);
                    l32[mi][0] += __low2float(p02) + __high2float(p02);
                    l32[mi][1] += __low2float(p13) + __high2float(p13);
                }
                #pragma unroll
                for (int dp = 0; dp < 4; dp++) {
                    const uint32_t offV =
                        swz((uint32_t)((hb * 64 + kc * 16 + vrow) * 128 + dp * 32 + vsel));
                    uint32_t v0, v1, v2, v3;
                    ldmx4t(v0, v1, v2, v3, st + 16384u + offV);
                    uint32_t bv0[2] = {v0, v1}, bv1[2] = {v2, v3};
                    mma16816(o[0][dp*2],   pa[0], bv0);
                    mma16816(o[0][dp*2+1], pa[0], bv1);
                    mma16816(o[1][dp*2],   pa[1], bv0);
                    mma16816(o[1][dp*2+1], pa[1], bv1);
                }
            }
        }

        __syncthreads();
        issueKV(kt + 4, kt + 4 < nkt);
    }

    // ---- epilogue: reduce row-sums over t4 quad, normalize, store ----
    #pragma unroll
    for (int mi = 0; mi < 2; mi++)
        #pragma unroll
        for (int h = 0; h < 2; h++) {
            float lsum = l32[mi][h];
            lsum += __shfl_xor_sync(0xffffffffu, lsum, 1);
            lsum += __shfl_xor_sync(0xffffffffu, lsum, 2);
            const float inv = 1.f / lsum;
            const int qg = q0 + wid * 32 + mi * 16 + g4 + h * 8;
            const size_t base = ((size_t)(b * SEQ + qg)) * EMBED + head * HDIM;
            #pragma unroll
            for (int ng = 0; ng < 8; ng++) {
                const float x = o[mi][ng][h * 2 + 0] * inv;
                const float y = o[mi][ng][h * 2 + 1] * inv;
                *(uint32_t*)(oh + base + ng * 8 + t4 * 2) = pack_h2(x, y);
            }
        }
}

// ---------------------------------------------------------------------------
extern "C" void kernel_launch(void* const* d_in, const int* in_sizes, int n_in,
                              void* d_out, int out_size)
{
    const float* key   = (const float*)d_in[0];
    const float* query = (const float*)d_in[1];
    const float* value = (const float*)d_in[2];
    const float* Wk    = (const float*)d_in[3];
    const float* Wq    = (const float*)d_in[4];
    const float* Wv    = (const float*)d_in[5];
    const float* Wo    = (const float*)d_in[6];
    float* out = (float*)d_out;

    __half *xa, *xb, *xc, *w0, *w1, *w2, *w3, *q16, *k16, *v16;
    cudaGetSymbolAddress((void**)&xa, g_xa);
    cudaGetSymbolAddress((void**)&xb, g_xb);
    cudaGetSymbolAddress((void**)&xc, g_xc);
    cudaGetSymbolAddress((void**)&w0, g_w0);
    cudaGetSymbolAddress((void**)&w1, g_w1);
    cudaGetSymbolAddress((void**)&w2, g_w2);
    cudaGetSymbolAddress((void**)&w3, g_w3);
    cudaGetSymbolAddress((void**)&q16, g_q16);
    cudaGetSymbolAddress((void**)&k16, g_k16);
    cudaGetSymbolAddress((void**)&v16, g_v16);

    cudaFuncSetAttribute(gemm_tc<true>,  cudaFuncAttributeMaxDynamicSharedMemorySize, GSMEM);
    cudaFuncSetAttribute(gemm_tc<false>, cudaFuncAttributeMaxDynamicSharedMemorySize, GSMEM);
    cudaFuncSetAttribute(flash_tc,       cudaFuncAttributeMaxDynamicSharedMemorySize, FSMEM);

    cvt_all<<<4096, 256>>>(query, key, value, Wq, Wk, Wv, Wo,
                           xa, xb, xc, w0, w1, w2, w3);

    gemm_tc<true><<<dim3(M_TOT/128, EMBED/128, 3), 256, GSMEM>>>(
        xa, xb, xc, w0, w1, w2, nullptr, q16, k16, v16);

    flash_tc<<<dim3(SEQ/256, BATCH*HEADS), 256, FSMEM>>>(q16, k16, v16, xa);

    gemm_tc<false><<<dim3(M_TOT/128, EMBED/128, 1), 256, GSMEM>>>(
        xa, xa, xa, w3, w3, w3, out, nullptr, nullptr, nullptr);
}

// round 14
// speedup vs baseline: 1.0950x; 1.0950x over previous
#include <cuda_runtime.h>
#include <cuda_fp16.h>
#include <math.h>
#include <stdint.h>

#define EMBED 1024
#define HEADS 16
#define HDIM  64
#define BATCH 2
#define SEQ   2048
#define M_TOT (BATCH*SEQ)   // 4096

// ---------------- scratch (device globals; allocation-free) ----------------
__device__ __align__(16) __half g_xa[M_TOT*EMBED];   // query act / AO
__device__ __align__(16) __half g_xb[M_TOT*EMBED];   // key act
__device__ __align__(16) __half g_xc[M_TOT*EMBED];   // value act
__device__ __align__(16) __half g_w0[EMBED*EMBED];   // Wq
__device__ __align__(16) __half g_w1[EMBED*EMBED];   // Wk
__device__ __align__(16) __half g_w2[EMBED*EMBED];   // Wv
__device__ __align__(16) __half g_w3[EMBED*EMBED];   // Wo
__device__ __align__(16) __half g_q16[BATCH*HEADS*SEQ*HDIM];
__device__ __align__(16) __half g_k16[BATCH*HEADS*SEQ*HDIM];
__device__ __align__(16) __half g_v16[BATCH*HEADS*SEQ*HDIM];

// ---------------------------------------------------------------------------
// fp32 -> fp16, ALL seven tensors in one launch.
// ---------------------------------------------------------------------------
__global__ __launch_bounds__(256) void cvt_all(
    const float* __restrict__ q,  const float* __restrict__ k,
    const float* __restrict__ v,
    const float* __restrict__ wq, const float* __restrict__ wk,
    const float* __restrict__ wv, const float* __restrict__ wo,
    __half* __restrict__ xa, __half* __restrict__ xb, __half* __restrict__ xc,
    __half* __restrict__ w0, __half* __restrict__ w1,
    __half* __restrict__ w2, __half* __restrict__ w3)
{
    const int blk = blockIdx.x;
    const float* x; __half* h; int off;
    if (blk < 1024)      { x = q;  h = xa; off = blk; }
    else if (blk < 2048) { x = k;  h = xb; off = blk - 1024; }
    else if (blk < 3072) { x = v;  h = xc; off = blk - 2048; }
    else if (blk < 3328) { x = wq; h = w0; off = blk - 3072; }
    else if (blk < 3584) { x = wk; h = w1; off = blk - 3328; }
    else if (blk < 3840) { x = wv; h = w2; off = blk - 3584; }
    else                 { x = wo; h = w3; off = blk - 3840; }

    const float4* src = (const float4*)x + (size_t)off * 1024;
    uint2* dst = (uint2*)h + (size_t)off * 1024;
    const int tid = threadIdx.x;
    #pragma unroll
    for (int j = 0; j < 4; j++) {
        float4 vv = src[j * 256 + tid];
        __half2 p = __floats2half2_rn(vv.x, vv.y);
        __half2 qq = __floats2half2_rn(vv.z, vv.w);
        uint2 r;
        r.x = reinterpret_cast<uint32_t&>(p);
        r.y = reinterpret_cast<uint32_t&>(qq);
        dst[j * 256 + tid] = r;
    }
}

// ---------------------------------------------------------------------------
// warp-MMA helpers
// ---------------------------------------------------------------------------
__device__ __forceinline__ uint32_t s2u(const void* p) {
    uint32_t a;
    asm("{ .reg .u64 t; cvta.to.shared.u64 t, %1; cvt.u32.u64 %0, t; }" : "=r"(a) : "l"(p));
    return a;
}

__device__ __forceinline__ void ldmx4(uint32_t& r0, uint32_t& r1, uint32_t& r2, uint32_t& r3,
                                      uint32_t addr)
{
    asm volatile("ldmatrix.sync.aligned.m8n8.x4.shared.b16 {%0,%1,%2,%3}, [%4];"
                 : "=r"(r0), "=r"(r1), "=r"(r2), "=r"(r3) : "r"(addr));
}

__device__ __forceinline__ void ldmx4t(uint32_t& r0, uint32_t& r1, uint32_t& r2, uint32_t& r3,
                                       uint32_t addr)
{
    asm volatile("ldmatrix.sync.aligned.m8n8.x4.trans.shared.b16 {%0,%1,%2,%3}, [%4];"
                 : "=r"(r0), "=r"(r1), "=r"(r2), "=r"(r3) : "r"(addr));
}

__device__ __forceinline__ void mma16816(float* d, const uint32_t* a, const uint32_t* b)
{
    asm volatile("mma.sync.aligned.m16n8k16.row.col.f32.f16.f16.f32 "
                 "{%0,%1,%2,%3}, {%4,%5,%6,%7}, {%8,%9}, {%0,%1,%2,%3};"
                 : "+f"(d[0]), "+f"(d[1]), "+f"(d[2]), "+f"(d[3])
                 : "r"(a[0]), "r"(a[1]), "r"(a[2]), "r"(a[3]), "r"(b[0]), "r"(b[1]));
}

__device__ __forceinline__ void cpasync16(uint32_t saddr, const void* gaddr)
{
    asm volatile("cp.async.cg.shared.global [%0], [%1], 16;" :: "r"(saddr), "l"(gaddr));
}

__device__ __forceinline__ uint32_t swz(uint32_t off) { return off ^ ((off >> 3) & 0x70); }

__device__ __forceinline__ uint32_t pack_h2(float x, float y) {
    __half2 t = __floats2half2_rn(x, y);
    return reinterpret_cast<uint32_t&>(t);
}

__device__ __forceinline__ uint32_t exp2_h2(float t0, float t1) {
    uint32_t r;
    asm("{ .reg .b32 t; cvt.rn.f16x2.f32 t, %2, %1; ex2.approx.f16x2 %0, t; }"
        : "=r"(r) : "f"(t0), "f"(t1));
    return r;
}

// ---------------------------------------------------------------------------
// Tensor-core GEMM: CTA tile 128x128, BK=64, 8 warps (2m x 4n), 3 smem
// stages with distance-2 issue => ONE __syncthreads per chunk.
// 2 CTAs/SM. blockIdx.z selects (X, W, out).
// ---------------------------------------------------------------------------
#define GSTG  32768u
#define GSMEM (3 * GSTG)   // 96 KB -> 2 CTAs/SM (192 KB)

template<bool SPLIT>
__global__ __launch_bounds__(256, 2) void gemm_tc(
    const __half* __restrict__ xa, const __half* __restrict__ xb, const __half* __restrict__ xc,
    const __half* __restrict__ wa, const __half* __restrict__ wb, const __half* __restrict__ wc,
    float* __restrict__ out,
    __half* __restrict__ oa, __half* __restrict__ ob, __half* __restrict__ oc)
{
    const int z = blockIdx.z;
    const __half* x16 = (z == 0) ? xa : (z == 1) ? xb : xc;
    const __half* w16 = (z == 0) ? wa : (z == 1) ? wb : wc;
    __half* outh      = (z == 0) ? oa : (z == 1) ? ob : oc;

    extern __shared__ char smg[];
    const uint32_t sb = s2u(smg);
    const int tid  = threadIdx.x;
    const int wid  = tid >> 5, lane = tid & 31;
    const int wm   = wid & 1;
    const int wn   = wid >> 1;
    const int m0   = blockIdx.x * 128;
    const int n0   = blockIdx.y * 128;

    const int ldr = tid >> 3;
    const int ldc = tid & 7;

    auto issue = [&](int c, int st, bool real) {
        if (real) {
            const uint32_t sst = sb + (uint32_t)st * GSTG;
            const int kc0 = c * 64;
            const __half* gA = x16 + (size_t)m0 * EMBED + kc0;
            const __half* gB = w16 + (size_t)n0 * EMBED + kc0;
            #pragma unroll
            for (int it = 0; it < 4; it++) {
                const int r = ldr + it * 32;
                const uint32_t o = swz((uint32_t)(r * 128 + ldc * 16));
                const size_t g = (size_t)r * EMBED + ldc * 8;
                cpasync16(sst +          o, gA + g);
                cpasync16(sst + 16384u + o, gB + g);
            }
        }
        asm volatile("cp.async.commit_group;" ::: "memory");
    };

    float d[4][4][4];
    #pragma unroll
    for (int mi = 0; mi < 4; mi++)
        #pragma unroll
        for (int ni = 0; ni < 4; ni++)
            #pragma unroll
            for (int r = 0; r < 4; r++) d[mi][ni][r] = 0.f;

    issue(0, 0, true); issue(1, 1, true);   // pending {0,1}

    const int arow = lane & 15;
    const int akc  = (lane & 16) >> 1;
    const int brow = (lane & 7) | ((lane & 16) >> 1);
    const int bkc  = lane & 8;

    const int NCHUNK = EMBED / 64;   // 16
    int cur = 0, nxt = 2;            // cur = stage of chunk c; nxt = stage for chunk c+2
    for (int c = 0; c < NCHUNK; c++) {
        asm volatile("cp.async.wait_group 1;" ::: "memory");   // chunk c complete
        __syncthreads();                                       // all warps done with stage nxt's old data

        // refill (stage nxt == stage of chunk c-1, proven drained by the sync above)
        issue(c + 2, nxt, c + 2 < NCHUNK);

        const uint32_t sst = sb + (uint32_t)cur * GSTG;
        const uint32_t bBase = sst + 16384u;

        #pragma unroll
        for (int ks = 0; ks < 4; ks++) {
            uint32_t a[4][4];
            #pragma unroll
            for (int mi = 0; mi < 4; mi++) {
                const int row = wm * 64 + mi * 16 + arow;
                const uint32_t off = swz((uint32_t)(row * 128 + (ks * 16 + akc) * 2));
                ldmx4(a[mi][0], a[mi][1], a[mi][2], a[mi][3], sst + off);
            }
            uint32_t b[4][2];
            #pragma unroll
            for (int bi = 0; bi < 2; bi++) {
                const int row = wn * 32 + bi * 16 + brow;
                const uint32_t off = swz((uint32_t)(row * 128 + (ks * 16 + bkc) * 2));
                uint32_t r0, r1, r2, r3;
                ldmx4(r0, r1, r2, r3, bBase + off);
                b[bi*2  ][0] = r0; b[bi*2  ][1] = r1;
                b[bi*2+1][0] = r2; b[bi*2+1][1] = r3;
            }
            #pragma unroll
            for (int mi = 0; mi < 4; mi++)
                #pragma unroll
                for (int ni = 0; ni < 4; ni++)
                    mma16816(d[mi][ni], a[mi], b[ni]);
        }

        cur = (cur == 2) ? 0 : cur + 1;
        nxt = (nxt == 2) ? 0 : nxt + 1;
    }

    const int g4 = lane >> 2, t4 = lane & 3;
    #pragma unroll
    for (int mi = 0; mi < 4; mi++) {
        #pragma unroll
        for (int half = 0; half < 2; half++) {
            const int m = m0 + wm * 64 + mi * 16 + g4 + half * 8;
            const int bb = m >> 11, ssq = m & (SEQ - 1);
            #pragma unroll
            for (int ni = 0; ni < 4; ni++) {
                const int n = n0 + wn * 32 + ni * 8 + t4 * 2;
                const float vx = d[mi][ni][half * 2 + 0];
                const float vy = d[mi][ni][half * 2 + 1];
                if (SPLIT) {
                    const int h = n >> 6, dd = n & 63;
                    const size_t idx = (((size_t)(bb * HEADS + h)) * SEQ + ssq) * HDIM + dd;
                    *(uint32_t*)(outh + idx) = pack_h2(vx, vy);
                } else {
                    float2 v; v.x = vx; v.y = vy;
                    *(float2*)(out + (size_t)m * EMBED + n) = v;
                }
            }
        }
    }
}

// ---------------------------------------------------------------------------
// Flash attention on HMMA — round-9 proven core (ones-MMA row-sum), with the
// single-sync pipeline: 4 stages, distance-3 issue right after the top sync.
// CTA: 128 q-rows; 8 warps x 16 q-rows x 128 kv; 1 CTA/SM.
// ---------------------------------------------------------------------------
#define FSTG  32768u
#define FSMEM (16384 + 4 * FSTG)
#define SCLOG2E 0.04508422002474647f   // (1/32) * log2(e)
#define MASK_RAW -3200000.0f           // -100000 / (1/32)

__global__ __launch_bounds__(256, 1) void flash_tc(
    const __half* __restrict__ q16, const __half* __restrict__ k16,
    const __half* __restrict__ v16, __half* __restrict__ oh)
{
    extern __shared__ char smf[];
    const uint32_t sb = s2u(smf);
    const int tid  = threadIdx.x;
    const int wid  = tid >> 5, lane = tid & 31;
    const int g4   = lane >> 2, t4 = lane & 3;
    const int bh   = blockIdx.y;
    const int b    = bh >> 4, head = bh & 15;
    const int qt   = (int)gridDim.x - 1 - (int)blockIdx.x;   // heavy tiles first
    const int q0   = qt * 128;

    const size_t bo = (size_t)bh * SEQ * HDIM;
    const __half* Qp = q16 + bo + (size_t)q0 * HDIM;
    const __half* Kp = k16 + bo;
    const __half* Vp = v16 + bo;

    const int ldr = tid >> 3, ldc = tid & 7;
    auto loadTile = [&](uint32_t dst, const __half* src) {
        #pragma unroll
        for (int it = 0; it < 4; it++) {
            const int r = ldr + it * 32;
            cpasync16(sb + dst + swz((uint32_t)(r * 128 + ldc * 16)),
                      src + (size_t)r * HDIM + ldc * 8);
        }
    };
    auto issueKV = [&](int kt, bool real) {
        if (real) {
            const uint32_t st = 16384u + (uint32_t)(kt & 3) * FSTG;
            const size_t off = (size_t)kt * 128 * HDIM;
            loadTile(st,           Kp + off);
            loadTile(st + 16384u,  Vp + off);
        }
        asm volatile("cp.async.commit_group;" ::: "memory");
    };

    loadTile(0u, Qp);               // group 0 bundles Q + KV0
    issueKV(0, true);
    issueKV(1, 1 <= qt);
    issueKV(2, 2 <= qt);
    // pending {0,1,2}

    const int arow = lane & 15;
    const int akc  = (lane & 16) >> 1;
    const int brow = (lane & 7) | ((lane & 16) >> 1);
    const int bkc  = lane & 8;
    const int vrow = lane & 15;
    const int vsel = ((lane >> 4) & 1) * 16;

    // wait for group 0 (Q + KV0) and hoist Q fragments
    asm volatile("cp.async.wait_group 2;" ::: "memory");
    __syncthreads();
    uint32_t qf[4][4];
    #pragma unroll
    for (int ks = 0; ks < 4; ks++) {
        const uint32_t offA = swz((uint32_t)((wid * 16 + arow) * 128 + (ks * 16 + akc) * 2));
        ldmx4(qf[ks][0], qf[ks][1], qf[ks][2], qf[ks][3], sb + offA);
    }

    // o[0..7]: output accumulators; o[8]: row-sum (P x ones)
    float o[9][4];
    #pragma unroll
    for (int ng = 0; ng < 9; ng++)
        #pragma unroll
        for (int r = 0; r < 4; r++) o[ng][r] = 0.f;
    float m_[2] = {-INFINITY, -INFINITY};

    const uint32_t ones2[2] = {0x3C003C00u, 0x3C003C00u};

    for (int kt = 0; kt <= qt; kt++) {
        asm volatile("cp.async.wait_group 2;" ::: "memory");   // tile kt ready
        __syncthreads();                                       // stage (kt-1)&3 drained

        // refill into stage (kt+3)&3 == (kt-1)&3 (freed by sync above)
        issueKV(kt + 3, kt + 3 <= qt);

        const uint32_t st = sb + 16384u + (uint32_t)(kt & 3) * FSTG;
        const bool diag = (kt == qt);
        const int k0 = kt * 128;

        float s[16][4];
        #pragma unroll
        for (int ni = 0; ni < 16; ni++)
            #pragma unroll
            for (int r = 0; r < 4; r++) s[ni][r] = 0.f;

        #pragma unroll
        for (int ks = 0; ks < 4; ks++) {
            #pragma unroll
            for (int bi = 0; bi < 8; bi++) {
                const uint32_t offB = swz((uint32_t)((bi * 16 + brow) * 128 + (ks * 16 + bkc) * 2));
                uint32_t r0, r1, r2, r3;
                ldmx4(r0, r1, r2, r3, st + offB);
                uint32_t b0[2] = {r0, r1}, b1[2] = {r2, r3};
                mma16816(s[bi*2],   qf[ks], b0);
                mma16816(s[bi*2+1], qf[ks], b1);
            }
        }

        if (diag) {
            #pragma unroll
            for (int ni = 0; ni < 16; ni++) {
                const int kg = k0 + ni * 8 + t4 * 2;
                #pragma unroll
                for (int h = 0; h < 2; h++) {
                    const int qg = q0 + wid * 16 + g4 + h * 8;
                    if (kg     > qg) s[ni][h*2+0] += MASK_RAW;
                    if (kg + 1 > qg) s[ni][h*2+1] += MASK_RAW;
                }
            }
        }
        #pragma unroll
        for (int h = 0; h < 2; h++) {
            float mx = -INFINITY;
            #pragma unroll
            for (int ni = 0; ni < 16; ni++)
                mx = fmaxf(mx, fmaxf(s[ni][h*2+0], s[ni][h*2+1]));
            mx = fmaxf(mx, __shfl_xor_sync(0xffffffffu, mx, 1));
            mx = fmaxf(mx, __shfl_xor_sync(0xffffffffu, mx, 2));
            const float mnew = fmaxf(m_[h], mx);
            const float corr = exp2f((m_[h] - mnew) * SCLOG2E);
            m_[h] = mnew;
            #pragma unroll
            for (int ng = 0; ng < 9; ng++) {
                o[ng][h*2+0] *= corr;
                o[ng][h*2+1] *= corr;
            }
        }

        const float lm0 = m_[0] * SCLOG2E;
        const float lm1 = m_[1] * SCLOG2E;
        #pragma unroll
        for (int kc = 0; kc < 8; kc++) {
            uint32_t pa[4];
            pa[0] = exp2_h2(fmaf(s[kc*2  ][0], SCLOG2E, -lm0),
                            fmaf(s[kc*2  ][1], SCLOG2E, -lm0));
            pa[1] = exp2_h2(fmaf(s[kc*2  ][2], SCLOG2E, -lm1),
                            fmaf(s[kc*2  ][3], SCLOG2E, -lm1));
            pa[2] = exp2_h2(fmaf(s[kc*2+1][0], SCLOG2E, -lm0),
                            fmaf(s[kc*2+1][1], SCLOG2E, -lm0));
            pa[3] = exp2_h2(fmaf(s[kc*2+1][2], SCLOG2E, -lm1),
                            fmaf(s[kc*2+1][3], SCLOG2E, -lm1));
            #pragma unroll
            for (int dp = 0; dp < 4; dp++) {
                const uint32_t offV = swz((uint32_t)((kc * 16 + vrow) * 128 + dp * 32 + vsel));
                uint32_t v0, v1, v2, v3;
                ldmx4t(v0, v1, v2, v3, st + 16384u + offV);
                uint32_t bv0[2] = {v0, v1}, bv1[2] = {v2, v3};
                mma16816(o[dp*2],   pa, bv0);
                mma16816(o[dp*2+1], pa, bv1);
            }
            mma16816(o[8], pa, ones2);
        }
        // no trailing sync — next iteration's top sync provides the barrier
    }

    #pragma unroll
    for (int h = 0; h < 2; h++) {
        const float inv = 1.f / o[8][h * 2];
        const int qg = q0 + wid * 16 + g4 + h * 8;
        const size_t base = ((size_t)(b * SEQ + qg)) * EMBED + head * HDIM;
        #pragma unroll
        for (int ng = 0; ng < 8; ng++) {
            const float x = o[ng][h * 2 + 0] * inv;
            const float y = o[ng][h * 2 + 1] * inv;
            *(uint32_t*)(oh + base + ng * 8 + t4 * 2) = pack_h2(x, y);
        }
    }
}

// ---------------------------------------------------------------------------
extern "C" void kernel_launch(void* const* d_in, const int* in_sizes, int n_in,
                              void* d_out, int out_size)
{
    const float* key   = (const float*)d_in[0];
    const float* query = (const float*)d_in[1];
    const float* value = (const float*)d_in[2];
    const float* Wk    = (const float*)d_in[3];
    const float* Wq    = (const float*)d_in[4];
    const float* Wv    = (const float*)d_in[5];
    const float* Wo    = (const float*)d_in[6];
    float* out = (float*)d_out;

    __half *xa, *xb, *xc, *w0, *w1, *w2, *w3, *q16, *k16, *v16;
    cudaGetSymbolAddress((void**)&xa, g_xa);
    cudaGetSymbolAddress((void**)&xb, g_xb);
    cudaGetSymbolAddress((void**)&xc, g_xc);
    cudaGetSymbolAddress((void**)&w0, g_w0);
    cudaGetSymbolAddress((void**)&w1, g_w1);
    cudaGetSymbolAddress((void**)&w2, g_w2);
    cudaGetSymbolAddress((void**)&w3, g_w3);
    cudaGetSymbolAddress((void**)&q16, g_q16);
    cudaGetSymbolAddress((void**)&k16, g_k16);
    cudaGetSymbolAddress((void**)&v16, g_v16);

    cudaFuncSetAttribute(gemm_tc<true>,  cudaFuncAttributeMaxDynamicSharedMemorySize, GSMEM);
    cudaFuncSetAttribute(gemm_tc<false>, cudaFuncAttributeMaxDynamicSharedMemorySize, GSMEM);
    cudaFuncSetAttribute(flash_tc,       cudaFuncAttributeMaxDynamicSharedMemorySize, FSMEM);

    cvt_all<<<4096, 256>>>(query, key, value, Wq, Wk, Wv, Wo,
                           xa, xb, xc, w0, w1, w2, w3);

    gemm_tc<true><<<dim3(M_TOT/128, EMBED/128, 3), 256, GSMEM>>>(
        xa, xb, xc, w0, w1, w2, nullptr, q16, k16, v16);

    flash_tc<<<dim3(SEQ/128, BATCH*HEADS), 256, FSMEM>>>(q16, k16, v16, xa);

    gemm_tc<false><<<dim3(M_TOT/128, EMBED/128, 1), 256, GSMEM>>>(
        xa, xa, xa, w3, w3, w3, out, nullptr, nullptr, nullptr);
}